// round 6
// baseline (speedup 1.0000x reference)
#include <cuda_runtime.h>

// KapoorConv 2-layer GCN, CSR-gather formulation (atomic-free aggregation).
//   deg[i] = 1 + indeg(i); dinv = rsqrt(deg)
//   t = dinv .* (X @ W)                    (rows pre-scaled by dinv)
//   acc_i = t_i + sum_{j->i} t_j           (self-loop + CSR gather)
//   layer1: h = relu(dinv .* acc)          layer2: out = dinv .* acc + b2

#define D      64
#define N_MAX  100000
#define E_MAX  1600000
#define SCAN_B 1024
#define NBLK   ((N_MAX + SCAN_B - 1) / SCAN_B)

__device__ int   g_cnt [N_MAX];
__device__ int   g_off [N_MAX];
__device__ int   g_cur [N_MAX];
__device__ int   g_bsum[NBLK];
__device__ float g_dinv[N_MAX];
__device__ int   g_esrc[E_MAX];
__device__ __align__(16) float g_t[N_MAX * D];
__device__ __align__(16) float g_h[N_MAX * D];

// ---------------- CSR build ----------------

__global__ void k_zero(int n) {
    int i = blockIdx.x * blockDim.x + threadIdx.x;
    if (i < n) g_cnt[i] = 0;
}

__global__ void k_count(const int* __restrict__ dst, int E) {
    int i = blockIdx.x * blockDim.x + threadIdx.x;
    if (i < E) atomicAdd(&g_cnt[dst[i]], 1);
}

__global__ void k_scan_part(int n) {
    __shared__ int s[SCAN_B];
    int t = threadIdx.x;
    int i = blockIdx.x * SCAN_B + t;
    int v = (i < n) ? g_cnt[i] : 0;
    s[t] = v;
    __syncthreads();
    for (int d = 1; d < SCAN_B; d <<= 1) {
        int add = (t >= d) ? s[t - d] : 0;
        __syncthreads();
        s[t] += add;
        __syncthreads();
    }
    if (i < n) g_off[i] = s[t] - v;              // exclusive
    if (t == SCAN_B - 1) g_bsum[blockIdx.x] = s[t];
}

__global__ void k_scan_tops(int B) {
    __shared__ int s[SCAN_B];
    int t = threadIdx.x;
    int v = (t < B) ? g_bsum[t] : 0;
    s[t] = v;
    __syncthreads();
    for (int d = 1; d < SCAN_B; d <<= 1) {
        int add = (t >= d) ? s[t - d] : 0;
        __syncthreads();
        s[t] += add;
        __syncthreads();
    }
    if (t < B) g_bsum[t] = s[t] - v;             // exclusive
}

__global__ void k_scan_add(int n) {              // finalize offsets + cursor + dinv
    int i = blockIdx.x * blockDim.x + threadIdx.x;
    if (i >= n) return;
    int o = g_off[i] + g_bsum[i / SCAN_B];
    g_off[i] = o;
    g_cur[i] = o;
    g_dinv[i] = rsqrtf(1.0f + (float)g_cnt[i]);
}

__global__ void k_fill(const int* __restrict__ src, const int* __restrict__ dst, int E) {
    int e = blockIdx.x * blockDim.x + threadIdx.x;
    if (e >= E) return;
    int pos = atomicAdd(&g_cur[dst[e]], 1);
    g_esrc[pos] = src[e];
}

// ---------------- GEMM: warp handles 8 rows, W in shared ----------------
// O[row] = dinv[row] * (X[row] @ W)

__global__ __launch_bounds__(256) void k_gemm(
    const float* __restrict__ X, const float* __restrict__ W,
    float* __restrict__ O, int n)
{
    __shared__ float Ws[D * D];
    for (int i = threadIdx.x; i < D * D; i += blockDim.x) Ws[i] = W[i];
    __syncthreads();

    int lane = threadIdx.x & 31;
    int wid  = blockIdx.x * (blockDim.x >> 5) + (threadIdx.x >> 5);
    int row0 = wid * 8;
    if (row0 >= n) return;
    int nr = min(8, n - row0);

    float xa[8], xb[8];
    float a0[8], a1[8];
#pragma unroll
    for (int r = 0; r < 8; ++r) {
        int row = row0 + ((r < nr) ? r : 0);
        xa[r] = X[row * D + lane];
        xb[r] = X[row * D + 32 + lane];
        a0[r] = 0.0f;
        a1[r] = 0.0f;
    }

    const float2* Ws2 = (const float2*)Ws;  // Ws2[k*32+lane] = W[k][2lane..2lane+1]
#pragma unroll
    for (int k = 0; k < 32; ++k) {
        float2 w = Ws2[k * 32 + lane];
#pragma unroll
        for (int r = 0; r < 8; ++r) {
            float xk = __shfl_sync(0xffffffffu, xa[r], k);
            a0[r] = fmaf(xk, w.x, a0[r]);
            a1[r] = fmaf(xk, w.y, a1[r]);
        }
    }
#pragma unroll
    for (int k = 0; k < 32; ++k) {
        float2 w = Ws2[(k + 32) * 32 + lane];
#pragma unroll
        for (int r = 0; r < 8; ++r) {
            float xk = __shfl_sync(0xffffffffu, xb[r], k);
            a0[r] = fmaf(xk, w.x, a0[r]);
            a1[r] = fmaf(xk, w.y, a1[r]);
        }
    }

#pragma unroll
    for (int r = 0; r < 8; ++r) {
        if (r >= nr) break;
        float s = g_dinv[row0 + r];
        float2 o;
        o.x = s * a0[r];
        o.y = s * a1[r];
        ((float2*)O)[(row0 + r) * 32 + lane] = o;
    }
}

// ---------------- CSR gather + fused epilogue ----------------
// FINAL=false: O = relu(dinv * acc)     FINAL=true: O = dinv * acc + b2

template <bool FINAL>
__global__ __launch_bounds__(256) void k_gather(
    const float* __restrict__ T, float* __restrict__ O,
    const float* __restrict__ b2, int n)
{
    int lane = threadIdx.x & 31;
    int row  = blockIdx.x * (blockDim.x >> 5) + (threadIdx.x >> 5);
    if (row >= n) return;

    const float2* T2 = (const float2*)T;
    float2 acc = __ldg(&T2[row * 32 + lane]);    // self-loop term
    int start = g_off[row];
    int cnt   = g_cnt[row];

    int j = 0;
    for (; j + 8 <= cnt; j += 8) {
        int s0 = __ldg(&g_esrc[start + j]);
        int s1 = __ldg(&g_esrc[start + j + 1]);
        int s2 = __ldg(&g_esrc[start + j + 2]);
        int s3 = __ldg(&g_esrc[start + j + 3]);
        int s4 = __ldg(&g_esrc[start + j + 4]);
        int s5 = __ldg(&g_esrc[start + j + 5]);
        int s6 = __ldg(&g_esrc[start + j + 6]);
        int s7 = __ldg(&g_esrc[start + j + 7]);
        float2 v0 = __ldg(&T2[s0 * 32 + lane]);
        float2 v1 = __ldg(&T2[s1 * 32 + lane]);
        float2 v2 = __ldg(&T2[s2 * 32 + lane]);
        float2 v3 = __ldg(&T2[s3 * 32 + lane]);
        float2 v4 = __ldg(&T2[s4 * 32 + lane]);
        float2 v5 = __ldg(&T2[s5 * 32 + lane]);
        float2 v6 = __ldg(&T2[s6 * 32 + lane]);
        float2 v7 = __ldg(&T2[s7 * 32 + lane]);
        acc.x += ((v0.x + v1.x) + (v2.x + v3.x)) + ((v4.x + v5.x) + (v6.x + v7.x));
        acc.y += ((v0.y + v1.y) + (v2.y + v3.y)) + ((v4.y + v5.y) + (v6.y + v7.y));
    }
    for (; j < cnt; ++j) {
        int s = __ldg(&g_esrc[start + j]);
        float2 v = __ldg(&T2[s * 32 + lane]);
        acc.x += v.x;
        acc.y += v.y;
    }

    float s = g_dinv[row];
    float2 o;
    if (FINAL) {
        o.x = fmaf(s, acc.x, __ldg(&b2[2 * lane]));
        o.y = fmaf(s, acc.y, __ldg(&b2[2 * lane + 1]));
    } else {
        o.x = fmaxf(s * acc.x, 0.0f);
        o.y = fmaxf(s * acc.y, 0.0f);
    }
    ((float2*)O)[row * 32 + lane] = o;
}

// ---------------- launch ----------------

extern "C" void kernel_launch(void* const* d_in, const int* in_sizes, int n_in,
                              void* d_out, int out_size)
{
    const float* x  = (const float*)d_in[0];   // [N, 64]
    const float* W1 = (const float*)d_in[1];   // [64, 64]
    const float* W2 = (const float*)d_in[2];   // [64, 64]
    const float* b2 = (const float*)d_in[3];   // [64]
    const int*   ei = (const int*)  d_in[4];   // [2, E]

    int n = in_sizes[0] / D;
    int E = in_sizes[4] / 2;
    const int* src = ei;
    const int* dst = ei + E;
    float* out = (float*)d_out;

    const int T = 256;
    int bN  = (n + T - 1) / T;
    int bE  = (E + T - 1) / T;
    int B   = (n + SCAN_B - 1) / SCAN_B;
    int bGm = (n + 63) / 64;                  // 8 warps * 8 rows per block
    int bGa = (n + 7) / 8;                    // 8 warps = 8 nodes per block

    // CSR build + dinv
    k_zero     <<<bN, T>>>(n);
    k_count    <<<bE, T>>>(dst, E);
    k_scan_part<<<B,  SCAN_B>>>(n);
    k_scan_tops<<<1,  SCAN_B>>>(B);
    k_scan_add <<<bN, T>>>(n);
    k_fill     <<<bE, T>>>(src, dst, E);

    // layer 1
    k_gemm          <<<bGm, T>>>(x, W1, g_t, n);
    k_gather<false> <<<bGa, T>>>(g_t, g_h, nullptr, n);

    // layer 2
    k_gemm          <<<bGm, T>>>(g_h, W2, g_t, n);
    k_gather<true>  <<<bGa, T>>>(g_t, out, b2, n);
}

// round 7
// speedup vs baseline: 18.2149x; 18.2149x over previous
#include <cuda_runtime.h>

// KapoorConv: 2-layer GCN forward (R5 scatter structure + 8-row GEMM).
//   deg[i] = 1 + indegree(i);  dinv = rsqrt(deg)
//   L1: t1 = dinv .* (x @ W1);  acc1 = t1 + scatter_add(t1[src] -> dst)
//       h  = relu(dinv .* acc1)
//   L2: t2 = dinv .* (h @ W2);  acc2 = t2 + scatter_add(t2[src] -> dst)
//       out = dinv .* acc2 + b2
// (dinv factored: pre-scale rows once, scatter unweighted, post-scale.)

#define D 64
#define N_MAX 100000

__device__ __align__(16) float g_deg [N_MAX];
__device__ __align__(16) float g_dinv[N_MAX];
__device__ __align__(16) float g_t1  [N_MAX * D];
__device__ __align__(16) float g_acc1[N_MAX * D];
__device__ __align__(16) float g_t2  [N_MAX * D];

// ---------------- degree / dinv ----------------

__global__ void k_deg_init(int n) {
    int i = blockIdx.x * blockDim.x + threadIdx.x;
    if (i < n) g_deg[i] = 1.0f;   // self-loop
}

__global__ void k_deg_count(const int* __restrict__ dst, int E) {
    int i = blockIdx.x * blockDim.x + threadIdx.x;
    if (i < E) atomicAdd(&g_deg[dst[i]], 1.0f);
}

__global__ void k_dinv(int n) {
    int i = blockIdx.x * blockDim.x + threadIdx.x;
    if (i < n) g_dinv[i] = rsqrtf(g_deg[i]);
}

// ---------------- GEMM: warp handles 8 rows, W in shared ----------------
// Rows pre-scaled by dinv; written to outA (gather source) and outB
// (accumulator init == self-loop term).
// PRE: input is prev layer's acc -> apply relu(dinv * v) on load.

template <bool PRE>
__device__ __forceinline__ void gemm_body(
    const float* __restrict__ X, const float* __restrict__ W,
    float* __restrict__ outA, float* __restrict__ outB, int n)
{
    __shared__ float Ws[D * D];
    for (int i = threadIdx.x; i < D * D; i += blockDim.x) Ws[i] = W[i];
    __syncthreads();

    int lane = threadIdx.x & 31;
    int wid  = blockIdx.x * (blockDim.x >> 5) + (threadIdx.x >> 5);
    int row0 = wid * 8;
    if (row0 >= n) return;
    int nr = min(8, n - row0);

    float xa[8], xb[8];
    float a0[8], a1[8];
#pragma unroll
    for (int r = 0; r < 8; ++r) {
        int row = row0 + ((r < nr) ? r : 0);
        float va = X[row * D + lane];
        float vb = X[row * D + 32 + lane];
        if (PRE) {
            float s = g_dinv[row];
            va = fmaxf(va * s, 0.0f);
            vb = fmaxf(vb * s, 0.0f);
        }
        xa[r] = va;
        xb[r] = vb;
        a0[r] = 0.0f;
        a1[r] = 0.0f;
    }

    const float2* Ws2 = (const float2*)Ws;  // Ws2[k*32+lane] = W[k][2lane..2lane+1]
#pragma unroll
    for (int k = 0; k < 32; ++k) {
        float2 w = Ws2[k * 32 + lane];
#pragma unroll
        for (int r = 0; r < 8; ++r) {
            float xk = __shfl_sync(0xffffffffu, xa[r], k);
            a0[r] = fmaf(xk, w.x, a0[r]);
            a1[r] = fmaf(xk, w.y, a1[r]);
        }
    }
#pragma unroll
    for (int k = 0; k < 32; ++k) {
        float2 w = Ws2[(k + 32) * 32 + lane];
#pragma unroll
        for (int r = 0; r < 8; ++r) {
            float xk = __shfl_sync(0xffffffffu, xb[r], k);
            a0[r] = fmaf(xk, w.x, a0[r]);
            a1[r] = fmaf(xk, w.y, a1[r]);
        }
    }

#pragma unroll
    for (int r = 0; r < 8; ++r) {
        if (r >= nr) break;
        float s = g_dinv[row0 + r];
        float2 o;
        o.x = s * a0[r];
        o.y = s * a1[r];
        ((float2*)outA)[(row0 + r) * 32 + lane] = o;
        ((float2*)outB)[(row0 + r) * 32 + lane] = o;
    }
}

__global__ __launch_bounds__(256) void k_gemm1(
    const float* __restrict__ X, const float* __restrict__ W, int n) {
    gemm_body<false>(X, W, g_t1, g_acc1, n);
}

__global__ __launch_bounds__(256) void k_gemm2(
    const float* __restrict__ W, float* __restrict__ out, int n) {
    gemm_body<true>(g_acc1, W, g_t2, out, n);
}

// ---------------- edge scatter: acc[dst] += T[src] ----------------
// 16 threads per edge, one float4 each. Unweighted (dinv folded into rows).

__device__ __forceinline__ void scatter_body(
    const int* __restrict__ src, const int* __restrict__ dst,
    const float4* __restrict__ T, float4* __restrict__ A, int E)
{
    unsigned t = blockIdx.x * blockDim.x + threadIdx.x;   // < E*16 = 25.6M, fits u32
    unsigned e = t >> 4;
    if (e >= (unsigned)E) return;
    unsigned c = t & 15u;
    int si = __ldg(&src[e]);
    int di = __ldg(&dst[e]);
    float4 v = __ldg(&T[(unsigned)si * 16u + c]);
    float4* p = A + ((unsigned)di * 16u + c);
    asm volatile("red.global.add.v4.f32 [%0], {%1,%2,%3,%4};"
                 :: "l"(p), "f"(v.x), "f"(v.y), "f"(v.z), "f"(v.w)
                 : "memory");
}

__global__ void k_scatter1(const int* __restrict__ src, const int* __restrict__ dst, int E) {
    scatter_body(src, dst, (const float4*)g_t1, (float4*)g_acc1, E);
}

__global__ void k_scatter2(const int* __restrict__ src, const int* __restrict__ dst,
                           float* __restrict__ out, int E) {
    scatter_body(src, dst, (const float4*)g_t2, (float4*)out, E);
}

// ---------------- finalize: out = dinv .* out + b2 ----------------

__global__ void k_final(float* __restrict__ out, const float* __restrict__ b2, int n) {
    int i = blockIdx.x * blockDim.x + threadIdx.x;
    if (i >= n * D) return;
    int row = i >> 6;
    int c   = i & 63;
    out[i] = g_dinv[row] * out[i] + b2[c];
}

// ---------------- launch ----------------

extern "C" void kernel_launch(void* const* d_in, const int* in_sizes, int n_in,
                              void* d_out, int out_size)
{
    const float* x  = (const float*)d_in[0];   // [N, 64]
    const float* W1 = (const float*)d_in[1];   // [64, 64]
    const float* W2 = (const float*)d_in[2];   // [64, 64]
    const float* b2 = (const float*)d_in[3];   // [64]
    const int*   ei = (const int*)  d_in[4];   // [2, E]

    int n = in_sizes[0] / D;
    int E = in_sizes[4] / 2;
    const int* src = ei;
    const int* dst = ei + E;
    float* out = (float*)d_out;

    const int T = 256;
    int bN    = (n + T - 1) / T;
    int bE    = (E + T - 1) / T;
    int bRows = (n + 63) / 64;                 // 8 warps * 8 rows per block
    long long sthreads = (long long)E * 16;
    int bScat = (int)((sthreads + T - 1) / T);
    int bElem = (n * D + T - 1) / T;

    k_deg_init <<<bN,    T>>>(n);
    k_deg_count<<<bE,    T>>>(dst, E);
    k_dinv     <<<bN,    T>>>(n);

    k_gemm1    <<<bRows, T>>>(x, W1, n);
    k_scatter1 <<<bScat, T>>>(src, dst, E);

    k_gemm2    <<<bRows, T>>>(W2, out, n);
    k_scatter2 <<<bScat, T>>>(src, dst, out, E);

    k_final    <<<bElem, T>>>(out, b2, n);
}